// round 2
// baseline (speedup 1.0000x reference)
#include <cuda_runtime.h>
#include <cstdint>

#define B_TOT   4096
#define N_IN    512
#define N_TOT   2048
#define N_EVAL  1536
#define N_OUTC  256
#define KNODES  64
#define NPHASES (N_EVAL / KNODES)   // 24
#define ROWS    32                  // batch rows per CTA
#define NCTAS   (B_TOT / ROWS)      // 128
#define NTHREADS 256
#define JC      64                  // j-chunk size

// Persistent activation matrix for evaluated nodes: [node][row], fp32.
__device__ float g_act[N_EVAL * B_TOT];

// ---- shared memory layout (floats) ----
#define SACT_SZ  (2 * JC * 33)              // double-buffered [2][JC][33] act tile
#define SW_OFF   (SACT_SZ)                  // 4224
#define SW_SZ    (2 * JC * 72)              // double-buffered [2][JC][72] W tile (padded, 16B-aligned rows)
#define SZ_OFF   (SW_OFF + SW_SZ)           // 13440
#define SZ_SZ    (ROWS * 65)
#define SWB_OFF  (SZ_OFF + SZ_SZ)           // 15520
#define SWB_SZ   (KNODES * 65)
#define SB_OFF   (SWB_OFF + SWB_SZ)         // 19680
#define SMEM_FLOATS (SB_OFF + KNODES)       // 19744
#define SMEM_BYTES  (SMEM_FLOATS * 4)       // 78976

__device__ __forceinline__ unsigned long long ffma2(unsigned long long a,
                                                    unsigned long long b,
                                                    unsigned long long c) {
    unsigned long long d;
    asm("fma.rn.f32x2 %0, %1, %2, %3;" : "=l"(d) : "l"(a), "l"(b), "l"(c));
    return d;
}
__device__ __forceinline__ unsigned long long splat2(float a) {
    unsigned long long d;
    asm("mov.b64 %0, {%1, %1};" : "=l"(d) : "f"(a));
    return d;
}
__device__ __forceinline__ float2 unpack2(unsigned long long v) {
    float2 r;
    asm("mov.b64 {%0, %1}, %2;" : "=f"(r.x), "=f"(r.y) : "l"(v));
    return r;
}
__device__ __forceinline__ float sigmoid5(float z) {
    float t5 = 5.0f * z;
    t5 = fminf(fmaxf(t5, -60.0f), 60.0f);           // match reference clip exactly
    float e;
    asm("ex2.approx.f32 %0, %1;" : "=f"(e) : "f"(t5 * (-1.4426950408889634f)));
    float den = 1.0f + e;
    float sig;
    asm("rcp.approx.f32 %0, %1;" : "=f"(sig) : "f"(den));
    return sig;
}

extern __shared__ float smem[];

__global__ void __launch_bounds__(NTHREADS)
ff_kernel(const float* __restrict__ x, const float* __restrict__ W,
          const float* __restrict__ bias, float* __restrict__ out) {
    const int t   = threadIdx.x;
    const int r0  = blockIdx.x * ROWS;
    const int row = t & 31;        // batch row within CTA tile
    const int cg  = t >> 5;        // 0..7 column group
    const int c0  = cg * 8;        // 8 node-columns per thread

    float* sAct = smem;             // [2][JC][33]
    float* sW   = smem + SW_OFF;    // [2][JC][72]
    float* sZ   = smem + SZ_OFF;    // [ROWS][65]
    float* sWb  = smem + SWB_OFF;   // [KNODES][65] in-block weights
    float* sB   = smem + SB_OFF;    // [KNODES] biases

    for (int p = 0; p < NPHASES; ++p) {
        const int e0 = p * KNODES;      // first eval-node index of this phase
        const int S  = N_IN + e0;       // number of already-known columns
        const int nchunks = S / JC;     // 8 + p (always exact)

        unsigned long long acc0 = 0ull, acc1 = 0ull, acc2 = 0ull, acc3 = 0ull;

        // ---- stage per-phase constants: in-block weights + biases ----
        for (int idx = t; idx < KNODES * KNODES; idx += NTHREADS) {
            int k = idx >> 6, j = idx & 63;
            sWb[k * 65 + j] = W[(e0 + k) * N_TOT + S + j];
        }
        if (t < KNODES) sB[t] = bias[e0 + t];

        // ---- stage helper ----
        auto stage = [&](int buf, int cidx) {
            float* dA = sAct + buf * (JC * 33);
            float* dW = sW   + buf * (JC * 72);
            const int jbase = cidx * JC;
            if (jbase < N_IN) {
                // source = x [B, 512] row-major: coalesce over jj
                for (int idx = t; idx < ROWS * JC; idx += NTHREADS) {
                    int r = idx >> 6, jj = idx & 63;
                    dA[jj * 33 + r] = x[(r0 + r) * N_IN + jbase + jj];
                }
            } else {
                // source = g_act [node][row]: coalesce over r
                for (int idx = t; idx < ROWS * JC; idx += NTHREADS) {
                    int jj = idx >> 5, r = idx & 31;
                    dA[jj * 33 + r] = g_act[(jbase - N_IN + jj) * B_TOT + r0 + r];
                }
            }
            // W tile: [64 nodes][64 j], coalesced over jj, stored transposed
            for (int idx = t; idx < KNODES * JC; idx += NTHREADS) {
                int k = idx >> 6, jj = idx & 63;
                dW[jj * 72 + k] = W[(e0 + k) * N_TOT + jbase + jj];
            }
        };

        stage(0, 0);
        __syncthreads();

        // ---- dense accumulation over history ----
        for (int c = 0; c < nchunks; ++c) {
            if (c + 1 < nchunks) stage((c + 1) & 1, c + 1);
            const float* sA  = sAct + (c & 1) * (JC * 33);
            const float* sWl = sW   + (c & 1) * (JC * 72);
            #pragma unroll 8
            for (int jj = 0; jj < JC; ++jj) {
                float a = sA[jj * 33 + row];
                unsigned long long a2 = splat2(a);
                const float* wp = sWl + jj * 72 + c0;
                ulonglong2 w01 = *(const ulonglong2*)(wp);
                ulonglong2 w23 = *(const ulonglong2*)(wp + 4);
                acc0 = ffma2(a2, w01.x, acc0);
                acc1 = ffma2(a2, w01.y, acc1);
                acc2 = ffma2(a2, w23.x, acc2);
                acc3 = ffma2(a2, w23.y, acc3);
            }
            __syncthreads();
        }

        // ---- write Z tile (+bias) to smem ----
        {
            float2 f0 = unpack2(acc0), f1 = unpack2(acc1);
            float2 f2 = unpack2(acc2), f3 = unpack2(acc3);
            float* zp = sZ + row * 65 + c0;
            zp[0] = f0.x + sB[c0 + 0]; zp[1] = f0.y + sB[c0 + 1];
            zp[2] = f1.x + sB[c0 + 2]; zp[3] = f1.y + sB[c0 + 3];
            zp[4] = f2.x + sB[c0 + 4]; zp[5] = f2.y + sB[c0 + 5];
            zp[6] = f3.x + sB[c0 + 6]; zp[7] = f3.y + sB[c0 + 7];
        }
        __syncthreads();

        // ---- serial in-block recurrence: one lane per batch row (warp 0) ----
        if (t < 32) {
            const int r = t;
            float o[KNODES];
            const float* zrow = sZ + r * 65;
            #pragma unroll
            for (int k = 0; k < KNODES; ++k) {
                float z  = zrow[k];
                float z1 = 0.0f;
                const float* wk = sWb + k * 65;
                #pragma unroll
                for (int j = 0; j + 1 < k; j += 2) {
                    z  = fmaf(o[j],     wk[j],     z);
                    z1 = fmaf(o[j + 1], wk[j + 1], z1);
                }
                if (k & 1) z = fmaf(o[k - 1], wk[k - 1], z);
                z += z1;
                o[k] = sigmoid5(z);
            }
            #pragma unroll
            for (int k = 0; k < KNODES; ++k) {
                g_act[(e0 + k) * B_TOT + r0 + r] = o[k];
                if (e0 + k >= N_EVAL - N_OUTC) {
                    out[(r0 + r) * N_OUTC + (e0 + k - (N_EVAL - N_OUTC))] = o[k];
                }
            }
        }
        __syncthreads();   // g_act writes visible (same SM) before next phase stages
    }
}

extern "C" void kernel_launch(void* const* d_in, const int* in_sizes, int n_in,
                              void* d_out, int out_size) {
    const float* x = (const float*)d_in[0];   // [4096, 512]
    const float* W = (const float*)d_in[1];   // [1536, 2048]
    const float* b = (const float*)d_in[2];   // [1536]
    float* out = (float*)d_out;               // [4096, 256]
    (void)in_sizes; (void)n_in; (void)out_size;

    cudaFuncSetAttribute(ff_kernel, cudaFuncAttributeMaxDynamicSharedMemorySize,
                         SMEM_BYTES);
    ff_kernel<<<NCTAS, NTHREADS, SMEM_BYTES>>>(x, W, b, out);
}

// round 3
// speedup vs baseline: 1.1276x; 1.1276x over previous
#include <cuda_runtime.h>
#include <cstdint>

#define B_TOT   4096
#define N_IN    512
#define N_TOT   2048
#define N_EVAL  1536
#define N_OUTC  256
#define KNODES  64
#define NPHASES 24
#define ROWS    32
#define NCTAS   128
#define NTHREADS 288          // 8 dense warps + 1 serial warp
#define DENSE_T 256

// Unified transposed activation store: g_all[node][batch], node 0..2047
// nodes 0..511 = x transposed; nodes 512..2047 = evaluated outputs.
__device__ float g_all[N_TOT * B_TOT];

// ---- shared memory layout (floats) ----
#define SA_OFF   0
#define SA_SZ    (2 * 64 * 33)       // 4224  double-buffered act tile [jj][33]
#define SW_OFF   (SA_OFF + SA_SZ)    // 4224
#define SW_SZ    (2 * 64 * 72)       // 9216  double-buffered W tile [jj][72]
#define SWL_OFF  (SW_OFF + SW_SZ)    // 13440 W tile for the dependent chunk
#define SWL_SZ   (64 * 72)
#define SO_OFF   (SWL_OFF + SWL_SZ)  // 18048 serial outputs [k][33]
#define SO_SZ    (64 * 33)
#define SZ_OFF   (SO_OFF + SO_SZ)    // 20160 Z tile [row][65]
#define SZ_SZ    (ROWS * 65)
#define SWB_OFF  (SZ_OFF + SZ_SZ)    // 22240 in-block weights [k][64]
#define SWB_SZ   (64 * 64)
#define SB_OFF   (SWB_OFF + SWB_SZ)  // 26336 biases
#define SMEM_FLOATS (SB_OFF + 64)    // 26400
#define SMEM_BYTES  (SMEM_FLOATS * 4)

#define BAR_ALL()   asm volatile("bar.sync 1, %0;" :: "n"(NTHREADS) : "memory")
#define BAR_DENSE() asm volatile("bar.sync 2, %0;" :: "n"(DENSE_T)  : "memory")

__device__ __forceinline__ unsigned long long ffma2(unsigned long long a,
                                                    unsigned long long b,
                                                    unsigned long long c) {
    unsigned long long d;
    asm("fma.rn.f32x2 %0, %1, %2, %3;" : "=l"(d) : "l"(a), "l"(b), "l"(c));
    return d;
}
__device__ __forceinline__ unsigned long long splat2(float a) {
    unsigned long long d;
    asm("mov.b64 %0, {%1, %1};" : "=l"(d) : "f"(a));
    return d;
}
__device__ __forceinline__ float2 unpack2(unsigned long long v) {
    float2 r;
    asm("mov.b64 {%0, %1}, %2;" : "=f"(r.x), "=f"(r.y) : "l"(v));
    return r;
}
__device__ __forceinline__ float sigmoid5(float z) {
    float t5 = 5.0f * z;
    t5 = fminf(fmaxf(t5, -60.0f), 60.0f);
    float e;
    asm("ex2.approx.f32 %0, %1;" : "=f"(e) : "f"(t5 * (-1.4426950408889634f)));
    float den = 1.0f + e;
    float sig;
    asm("rcp.approx.f32 %0, %1;" : "=f"(sig) : "f"(den));
    return sig;
}

// ---- x transpose: x[4096][512] -> g_all[j][b] for j < 512 ----
__global__ void __launch_bounds__(256) transpose_x(const float* __restrict__ x) {
    __shared__ float tile[32][33];
    const int jb = blockIdx.x * 32;   // 16
    const int bb = blockIdx.y * 32;   // 128
    const int tx = threadIdx.x, ty = threadIdx.y;   // 32 x 8
    #pragma unroll
    for (int i = 0; i < 32; i += 8)
        tile[ty + i][tx] = x[(bb + ty + i) * N_IN + jb + tx];
    __syncthreads();
    #pragma unroll
    for (int i = 0; i < 32; i += 8)
        g_all[(jb + ty + i) * B_TOT + bb + tx] = tile[tx][ty + i];
}

extern __shared__ float smem[];

__global__ void __launch_bounds__(NTHREADS)
ff_kernel(const float* __restrict__ W, const float* __restrict__ bias,
          float* __restrict__ out) {
    const int t  = threadIdx.x;
    const int r0 = blockIdx.x * ROWS;

    float* sA   = smem + SA_OFF;
    float* sW   = smem + SW_OFF;
    float* sWl  = smem + SWL_OFF;
    float* sO   = smem + SO_OFF;
    float* sZ   = smem + SZ_OFF;
    float* sWb  = smem + SWB_OFF;
    float* sB   = smem + SB_OFF;

    if (t < DENSE_T) {
        // ================== DENSE WARPS ==================
        const int row = t & 31;
        const int c0  = (t >> 5) * 8;

        unsigned long long acc0 = 0ull, acc1 = 0ull, acc2 = 0ull, acc3 = 0ull;

        auto stage_act = [&](float* dst, int jbase) {
            #pragma unroll
            for (int idx = t; idx < 2048; idx += DENSE_T) {
                int jj = idx >> 5, r = idx & 31;
                dst[jj * 33 + r] = g_all[(jbase + jj) * B_TOT + r0 + r];
            }
        };
        auto stage_W = [&](float* dst, int jbase, int e0w) {
            #pragma unroll
            for (int idx = t; idx < 4096; idx += DENSE_T) {
                int k = idx >> 6, jj = idx & 63;
                dst[jj * 72 + k] = W[(e0w + k) * N_TOT + jbase + jj];
            }
        };
        auto mac_tile = [&](const float* sa, const float* sw) {
            #pragma unroll 8
            for (int jj = 0; jj < 64; ++jj) {
                float a = sa[jj * 33 + row];
                unsigned long long a2 = splat2(a);
                const float* wp = sw + jj * 72 + c0;
                ulonglong2 w01 = *(const ulonglong2*)(wp);
                ulonglong2 w23 = *(const ulonglong2*)(wp + 4);
                acc0 = ffma2(a2, w01.x, acc0);
                acc1 = ffma2(a2, w01.y, acc1);
                acc2 = ffma2(a2, w23.x, acc2);
                acc3 = ffma2(a2, w23.y, acc3);
            }
        };

        // -------- prologue: chunks 0..6 of phase 0 (all from x) --------
        stage_act(sA, 0);
        stage_W(sW, 0, 0);
        BAR_DENSE();
        for (int c = 0; c < 7; ++c) {
            if (c < 6) {
                int b = (c + 1) & 1;
                stage_act(sA + b * (64 * 33), (c + 1) * 64);
                stage_W(sW + b * (64 * 72), (c + 1) * 64, 0);
            }
            mac_tile(sA + (c & 1) * (64 * 33), sW + (c & 1) * (64 * 72));
            BAR_DENSE();
        }
        // dependent-chunk operands for phase 0: act cols 448..511, W rows 0..63
        stage_act(sO, 448);
        stage_W(sWl, 448, 0);
        BAR_DENSE();

        for (int p = 0; p < NPHASES; ++p) {
            const int e0 = p * KNODES;
            const int S  = N_IN + e0;

            // ---- segment A: in-block weights + dependent chunk ----
            #pragma unroll
            for (int idx = t; idx < 4096; idx += DENSE_T) {
                int k = idx >> 6, j = idx & 63;
                sWb[k * 64 + j] = W[(e0 + k) * N_TOT + S + j];
            }
            if (t < 64) sB[t] = bias[e0 + t];
            mac_tile(sO, sWl);
            BAR_DENSE();                 // sB/sWb visible to dense; mac done

            {   // Z = acc + bias -> sZ
                float2 f0 = unpack2(acc0), f1 = unpack2(acc1);
                float2 f2 = unpack2(acc2), f3 = unpack2(acc3);
                float* zp = sZ + row * 65 + c0;
                zp[0] = f0.x + sB[c0 + 0]; zp[1] = f0.y + sB[c0 + 1];
                zp[2] = f1.x + sB[c0 + 2]; zp[3] = f1.y + sB[c0 + 3];
                zp[4] = f2.x + sB[c0 + 4]; zp[5] = f2.y + sB[c0 + 5];
                zp[6] = f3.x + sB[c0 + 6]; zp[7] = f3.y + sB[c0 + 7];
            }
            acc0 = acc1 = acc2 = acc3 = 0ull;
            BAR_ALL();                   // serial warp may start on sZ/sWb

            // ---- segment B: accumulate phase p+1 independent chunks ----
            if (p < NPHASES - 1) {
                const int nch = 8 + p;           // chunks 0..nch-1 = cols 0..S_p-1
                const int e0n = e0 + KNODES;     // W rows of phase p+1
                stage_act(sA, 0);
                stage_W(sW, 0, e0n);
                BAR_DENSE();
                for (int c = 0; c < nch; ++c) {
                    if (c + 1 < nch) {
                        int b = (c + 1) & 1;
                        stage_act(sA + b * (64 * 33), (c + 1) * 64);
                        stage_W(sW + b * (64 * 72), (c + 1) * 64, e0n);
                    } else {
                        // prefetch next dependent-chunk W (block p cols)
                        stage_W(sWl, S, e0n);
                    }
                    mac_tile(sA + (c & 1) * (64 * 33), sW + (c & 1) * (64 * 72));
                    BAR_DENSE();
                }
            }
            BAR_ALL();                   // phase end: serial done, sO ready
        }
    } else {
        // ================== SERIAL WARP ==================
        const int r = t - DENSE_T;       // 0..31
        for (int p = 0; p < NPHASES; ++p) {
            const int e0 = p * KNODES;
            BAR_ALL();                   // wait: sZ + sWb ready

            float o[KNODES];
            const float* zrow = sZ + r * 65;
            #pragma unroll
            for (int k = 0; k < KNODES; ++k) {
                float z  = zrow[k];
                float z1 = 0.0f;
                const float* wk = sWb + k * 64;
                #pragma unroll
                for (int j = 0; j + 1 < k; j += 2) {
                    z  = fmaf(o[j],     wk[j],     z);
                    z1 = fmaf(o[j + 1], wk[j + 1], z1);
                }
                if (k & 1) z = fmaf(o[k - 1], wk[k - 1], z);
                z += z1;
                o[k] = sigmoid5(z);
            }
            #pragma unroll
            for (int k = 0; k < KNODES; ++k) {
                sO[k * 33 + r] = o[k];
                g_all[(N_IN + e0 + k) * B_TOT + r0 + r] = o[k];
                if (e0 + k >= N_EVAL - N_OUTC) {
                    out[(r0 + r) * N_OUTC + (e0 + k - (N_EVAL - N_OUTC))] = o[k];
                }
            }
            __threadfence_block();       // order g_all stores before barrier
            BAR_ALL();                   // phase end
        }
    }
}

extern "C" void kernel_launch(void* const* d_in, const int* in_sizes, int n_in,
                              void* d_out, int out_size) {
    const float* x = (const float*)d_in[0];   // [4096, 512]
    const float* W = (const float*)d_in[1];   // [1536, 2048]
    const float* b = (const float*)d_in[2];   // [1536]
    float* out = (float*)d_out;               // [4096, 256]
    (void)in_sizes; (void)n_in; (void)out_size;

    dim3 tg(16, 128), tb(32, 8);
    transpose_x<<<tg, tb>>>(x);

    cudaFuncSetAttribute(ff_kernel, cudaFuncAttributeMaxDynamicSharedMemorySize,
                         SMEM_BYTES);
    ff_kernel<<<NCTAS, NTHREADS, SMEM_BYTES>>>(W, b, out);
}

// round 6
// speedup vs baseline: 4.6701x; 4.1417x over previous
#include <cuda_runtime.h>
#include <cuda_bf16.h>
#include <cstdint>

#define B_TOT   4096
#define N_IN    512
#define N_TOT   2048
#define N_EVAL  1536
#define N_OUTC  256
#define NPH     24
#define MROWS   32
#define NCTA    128
#define NTHREADS 160      // warps 0-3 compute, warp 4 serial

// Pre-baked bf16 hi/lo tiles, stride-72 rows (144 B) for conflict-free LDS.
// A tile (per rowblock, per 64-col chunk): hi[32*72] + lo[32*72] = 9216 B
// B tile (per phase, per chunk):           hi[64*72] + lo[64*72] = 18432 B
__device__ __align__(256) char g_AT[128u * 32u * 9216u];    // ~36 MB
__device__ __align__(256) char g_BT[24u * 32u * 18432u];    // ~14 MB

#define AT_TILE(rb, c) (g_AT + (size_t)((rb) * 32 + (c)) * 9216u)
#define BT_TILE(q, c)  (g_BT + (size_t)((q) * 32 + (c)) * 18432u)

// ---- shared memory layout (bytes) ----
#define SM_A    0         // 2 x 9216   A double buffer (hi|lo)
#define SM_B    18432     // 2 x 18432  B double buffer (hi|lo)
#define SM_DEPA 55296     // 9216       dep-chunk A (written ONLY by serial warp)
#define SM_DEPB 64512     // 18432      dep-chunk B
#define SM_SWB  82944     // 16384      in-block weights f32 [64][64]
#define SM_SB   99328     // 256        biases f32 [64]
#define SM_SZ   99584     // 32*65*4    Z tile f32 [32][65]
#define SMEM_BYTES 107904

#define BAR_ALL()   asm volatile("bar.sync 1, 160;" ::: "memory")
#define BAR_DENSE() asm volatile("bar.sync 2, 128;" ::: "memory")
#define CP_COMMIT() asm volatile("cp.async.commit_group;" ::: "memory")
#define CP_WAIT0()  asm volatile("cp.async.wait_group 0;" ::: "memory")
#define CP_WAIT1()  asm volatile("cp.async.wait_group 1;" ::: "memory")

__device__ __forceinline__ uint32_t smem_u32(const void* p) {
    uint32_t a;
    asm("{ .reg .u64 t; cvta.to.shared.u64 t, %1; cvt.u32.u64 %0, t; }"
        : "=r"(a) : "l"(p));
    return a;
}
__device__ __forceinline__ void cp16(uint32_t d, const void* s) {
    asm volatile("cp.async.cg.shared.global [%0], [%1], 16;"
                 :: "r"(d), "l"(s) : "memory");
}
__device__ __forceinline__ void hmma(float* d, const uint32_t* a, const uint32_t* b) {
    asm volatile("mma.sync.aligned.m16n8k16.row.col.f32.bf16.bf16.f32 "
                 "{%0,%1,%2,%3}, {%4,%5,%6,%7}, {%8,%9}, {%0,%1,%2,%3};"
                 : "+f"(d[0]), "+f"(d[1]), "+f"(d[2]), "+f"(d[3])
                 : "r"(a[0]), "r"(a[1]), "r"(a[2]), "r"(a[3]),
                   "r"(b[0]), "r"(b[1]));
}
__device__ __forceinline__ uint32_t pack2(__nv_bfloat16 a, __nv_bfloat16 b) {
    return (uint32_t)__bfloat16_as_ushort(a) |
           ((uint32_t)__bfloat16_as_ushort(b) << 16);
}
__device__ __forceinline__ void split_pack(float v0, float v1,
                                           uint32_t& hp, uint32_t& lp) {
    __nv_bfloat16 h0 = __float2bfloat16(v0), h1 = __float2bfloat16(v1);
    __nv_bfloat16 l0 = __float2bfloat16(v0 - __bfloat162float(h0));
    __nv_bfloat16 l1 = __float2bfloat16(v1 - __bfloat162float(h1));
    hp = pack2(h0, h1); lp = pack2(l0, l1);
}
__device__ __forceinline__ float sigmoid5(float z) {
    float t5 = fminf(fmaxf(5.0f * z, -60.0f), 60.0f);
    float e;
    asm("ex2.approx.f32 %0, %1;" : "=f"(e) : "f"(t5 * (-1.4426950408889634f)));
    float sig;
    asm("rcp.approx.f32 %0, %1;" : "=f"(sig) : "f"(1.0f + e));
    return sig;
}

// ---- prep: bake pre-packed hi/lo bf16 tiles ----
__global__ void __launch_bounds__(256) prep_X(const float* __restrict__ x) {
    const int rb = blockIdx.x, c = blockIdx.y;   // 128 x 8
    char* baseH = AT_TILE(rb, c);
    char* baseL = baseH + 4608;
    for (int i = threadIdx.x; i < 32 * 32; i += 256) {
        int r = i >> 5, kp = i & 31;
        const float* src = x + (size_t)(rb * 32 + r) * N_IN + c * 64 + kp * 2;
        uint32_t hp, lp; split_pack(src[0], src[1], hp, lp);
        uint32_t off = (uint32_t)(r * 144 + kp * 4);
        *(uint32_t*)(baseH + off) = hp;
        *(uint32_t*)(baseL + off) = lp;
    }
}
__global__ void __launch_bounds__(256) prep_W(const float* __restrict__ W) {
    const int q = blockIdx.x, c = blockIdx.y;    // 24 x 32
    if (c > 7 + q) return;
    char* baseH = BT_TILE(q, c);
    char* baseL = baseH + 9216;
    for (int i = threadIdx.x; i < 64 * 32; i += 256) {
        int n = i >> 5, kp = i & 31;
        const float* src = W + (size_t)(q * 64 + n) * N_TOT + c * 64 + kp * 2;
        uint32_t hp, lp; split_pack(src[0], src[1], hp, lp);
        uint32_t off = (uint32_t)(n * 144 + kp * 4);
        *(uint32_t*)(baseH + off) = hp;
        *(uint32_t*)(baseL + off) = lp;
    }
}

extern __shared__ __align__(16) char smem[];

__global__ void __launch_bounds__(NTHREADS, 1)
ff_kernel(const float* __restrict__ W, const float* __restrict__ bias,
          float* __restrict__ out) {
    const int t = threadIdx.x;
    const int wid = t >> 5, lane = t & 31;
    const int rb = blockIdx.x;
    const uint32_t sb32 = smem_u32(smem);
    float* sZ  = (float*)(smem + SM_SZ);
    float* sWb = (float*)(smem + SM_SWB);
    float* sB  = (float*)(smem + SM_SB);

    if (wid < 4) {
        // =================== COMPUTE WARPS ===================
        const int row0 = (wid & 1) * 16;
        const int col0 = (wid >> 1) * 32;
        float acc[4][4] = {};

        auto pf_A = [&](uint32_t doff, const char* src) {
            for (int i = t; i < 576; i += 128) cp16(sb32 + doff + i * 16, src + i * 16);
        };
        auto pf_B = [&](uint32_t doff, const char* src) {
            for (int i = t; i < 1152; i += 128) cp16(sb32 + doff + i * 16, src + i * 16);
        };
        auto mac_chunk = [&](const char* A, const char* Bt) {
            #pragma unroll
            for (int kk = 0; kk < 4; ++kk) {
                const char* pa = A + (row0 + (lane >> 2)) * 144 + (lane & 3) * 4 + kk * 32;
                uint32_t ah[4] = { *(const uint32_t*)(pa),
                                   *(const uint32_t*)(pa + 1152),
                                   *(const uint32_t*)(pa + 16),
                                   *(const uint32_t*)(pa + 1168) };
                const char* pl = pa + 4608;
                uint32_t al[4] = { *(const uint32_t*)(pl),
                                   *(const uint32_t*)(pl + 1152),
                                   *(const uint32_t*)(pl + 16),
                                   *(const uint32_t*)(pl + 1168) };
                #pragma unroll
                for (int nt = 0; nt < 4; ++nt) {
                    const char* pb = Bt + (col0 + nt * 8 + (lane >> 2)) * 144
                                     + (lane & 3) * 4 + kk * 32;
                    uint32_t bh[2] = { *(const uint32_t*)(pb),
                                       *(const uint32_t*)(pb + 16) };
                    uint32_t bl[2] = { *(const uint32_t*)(pb + 9216),
                                       *(const uint32_t*)(pb + 9232) };
                    hmma(acc[nt], ah, bh);
                    hmma(acc[nt], ah, bl);
                    hmma(acc[nt], al, bh);
                }
            }
        };
        auto chunk_loop = [&](int q, int nch, bool doDep) {
            pf_A(SM_A, AT_TILE(rb, 0));
            pf_B(SM_B, BT_TILE(q, 0));
            CP_COMMIT();
            for (int c = 0; c < nch; ++c) {
                bool committed = false;
                if (c + 1 < nch) {
                    uint32_t bsel = (uint32_t)((c + 1) & 1);
                    pf_A(SM_A + bsel * 9216u,  AT_TILE(rb, c + 1));
                    pf_B(SM_B + bsel * 18432u, BT_TILE(q, c + 1));
                    CP_COMMIT(); committed = true;
                } else if (doDep) {
                    // Dep-chunk B (weights) only. Dep-chunk A lives in SM_DEPA,
                    // written DIRECTLY by the serial warp this phase — never
                    // prefetch it from global (that was the R4 race).
                    pf_B(SM_DEPB, BT_TILE(q, 7 + q));
                    CP_COMMIT(); committed = true;
                }
                if (committed) CP_WAIT1(); else CP_WAIT0();
                BAR_DENSE();
                mac_chunk(smem + SM_A + (size_t)(c & 1) * 9216u,
                          smem + SM_B + (size_t)(c & 1) * 18432u);
                BAR_DENSE();
            }
        };

        // ---- prologue: phase 0 (8 chunks, all from x) ----
        chunk_loop(0, 8, false);

        for (int p = 0; p < NPH; ++p) {
            const int e0 = p * 64, S = N_IN + e0;

            // segment A: stage sWb/sB, dep mma, Z write
            for (int i = t; i < 1024; i += 128) {
                int n = i >> 4, j = i & 15;
                cp16(sb32 + SM_SWB + (uint32_t)i * 16,
                     W + (size_t)(e0 + n) * N_TOT + S + j * 4);
            }
            if (t < 16) cp16(sb32 + SM_SB + (uint32_t)t * 16, bias + e0 + t * 4);
            CP_COMMIT();
            CP_WAIT0();
            BAR_DENSE();
            if (p > 0) mac_chunk(smem + SM_DEPA, smem + SM_DEPB);
            {
                int r = row0 + (lane >> 2), cb = (lane & 3) * 2;
                #pragma unroll
                for (int nt = 0; nt < 4; ++nt) {
                    float* z = sZ + r * 65 + col0 + nt * 8 + cb;
                    z[0] = acc[nt][0]; z[1] = acc[nt][1];
                    z[8 * 65] = acc[nt][2]; z[8 * 65 + 1] = acc[nt][3];
                    acc[nt][0] = acc[nt][1] = acc[nt][2] = acc[nt][3] = 0.f;
                }
            }
            BAR_ALL();     // serial warp may start

            if (p < NPH - 1)
                chunk_loop(p + 1, 8 + p, true);
            BAR_ALL();     // phase end (serial done; SM_DEPA ready)
        }
    } else {
        // =================== SERIAL WARP (lane = row) ===================
        const int r = lane;
        for (int p = 0; p < NPH; ++p) {
            const int e0 = p * 64;
            BAR_ALL();     // Z + sWb + sB ready

            float o[64];
            const float* zrow = sZ + r * 65;
            #pragma unroll
            for (int k = 0; k < 64; ++k) {
                float z  = zrow[k] + sB[k];
                float z1 = 0.0f;
                const float* wk = sWb + k * 64;
                #pragma unroll
                for (int j = 0; j + 1 < k; j += 2) {
                    z  = fmaf(o[j],     wk[j],     z);
                    z1 = fmaf(o[j + 1], wk[j + 1], z1);
                }
                if (k & 1) z = fmaf(o[k - 1], wk[k - 1], z);
                o[k] = sigmoid5(z + z1);
            }

            if (p < NPH - 1) {
                // block outputs -> dep A tile (smem, sole source for next phase)
                //                + global A tile (chunk 8+p, for phases >= p+2)
                char* sH = smem + SM_DEPA;
                char* gH = AT_TILE(rb, 8 + p);
                #pragma unroll
                for (int kp = 0; kp < 32; ++kp) {
                    uint32_t hp, lp;
                    split_pack(o[2 * kp], o[2 * kp + 1], hp, lp);
                    uint32_t off = (uint32_t)(r * 144 + kp * 4);
                    *(uint32_t*)(sH + off) = hp;
                    *(uint32_t*)(sH + off + 4608) = lp;
                    *(uint32_t*)(gH + off) = hp;
                    *(uint32_t*)(gH + off + 4608) = lp;
                }
            }
            if (p >= 20) {
                float* orow = out + (size_t)(rb * 32 + r) * N_OUTC + (e0 - 1280);
                #pragma unroll
                for (int k = 0; k < 64; ++k) orow[k] = o[k];
            }
            __threadfence();   // g_AT writes visible to later cp.async (L2 path)
            BAR_ALL();         // phase end
        }
    }
}

extern "C" void kernel_launch(void* const* d_in, const int* in_sizes, int n_in,
                              void* d_out, int out_size) {
    const float* x = (const float*)d_in[0];   // [4096, 512]
    const float* W = (const float*)d_in[1];   // [1536, 2048]
    const float* b = (const float*)d_in[2];   // [1536]
    float* out = (float*)d_out;               // [4096, 256]
    (void)in_sizes; (void)n_in; (void)out_size;

    prep_X<<<dim3(128, 8), 256>>>(x);
    prep_W<<<dim3(24, 32), 256>>>(W);

    cudaFuncSetAttribute(ff_kernel, cudaFuncAttributeMaxDynamicSharedMemorySize,
                         SMEM_BYTES);
    ff_kernel<<<NCTA, NTHREADS, SMEM_BYTES>>>(W, b, out);
}